// round 3
// baseline (speedup 1.0000x reference)
#include <cuda_runtime.h>
#include <cuda_bf16.h>
#include <math.h>

#define B_    256
#define M_    196
#define E_    1024
#define H_    8
#define DH_   128
#define MID_  64
#define NBIG  (B_ * M_)   // 50176

// ---------------- persistent scratch (no allocations allowed) -----------------
__device__ float g_kt [(size_t)NBIG * E_];   // k  [B,H,M,Dh]
__device__ float g_v2t[(size_t)NBIG * E_];   // v2 [B,H,M,Dh]
__device__ float g_qt [(size_t)B_ * E_];     // q  [B,H,Dh]
__device__ float g_v1t[(size_t)B_ * E_];     // v1 [B,H,Dh]

// ---------------- smem layout constants (in 32-bit words) ---------------------
// per buffer: Ahi[2112] Alo[2112] Bhi[2112] Blo[2112]  (ABLK=33 padded blocks)
#define ABLK      33
#define A_WORDS   2112      // 16 blocks * 33 * 4
#define B_WORDS   2112      // 32 blocks * 33 * 2
#define BUF_WORDS 8448
#define SMEM_BYTES (2 * BUF_WORDS * 4)   // 67584

__device__ __forceinline__ void split2(float f0, float f1,
                                       unsigned &hi, unsigned &lo)
{
    __nv_bfloat16 h0 = __float2bfloat16(f0);
    __nv_bfloat16 h1 = __float2bfloat16(f1);
    float r0 = f0 - __bfloat162float(h0);
    float r1 = f1 - __bfloat162float(h1);
    __nv_bfloat16 l0 = __float2bfloat16(r0);
    __nv_bfloat16 l1 = __float2bfloat16(r1);
    hi = (unsigned)__bfloat16_as_ushort(h0) |
         ((unsigned)__bfloat16_as_ushort(h1) << 16);
    lo = (unsigned)__bfloat16_as_ushort(l0) |
         ((unsigned)__bfloat16_as_ushort(l1) << 16);
}

__device__ __forceinline__ void mma16816(float* c, uint4 a, uint2 b)
{
    asm volatile(
        "mma.sync.aligned.m16n8k16.row.col.f32.bf16.bf16.f32 "
        "{%0,%1,%2,%3}, {%4,%5,%6,%7}, {%8,%9}, {%0,%1,%2,%3};\n"
        : "+f"(c[0]), "+f"(c[1]), "+f"(c[2]), "+f"(c[3])
        : "r"(a.x), "r"(a.y), "r"(a.z), "r"(a.w), "r"(b.x), "r"(b.y));
}

// =============================================================================
// GEMM (rows x 1024) @ (1024 x 1024) + bias, then CELU + GroupNorm over the
// 128-col tile (== one group) + transposed store out[((b*H+g)*Mp + m)*128 + c].
// Block tile 128x128, BK=32, 8 warps (2x4), warp tile 64x32, bf16x3 mma.
// =============================================================================
__global__ __launch_bounds__(256) void gemm_fused(
    const float* __restrict__ A, const float* __restrict__ W,
    const float* __restrict__ bias, const float* __restrict__ gw,
    const float* __restrict__ gb, float* __restrict__ out, int Mp)
{
    extern __shared__ unsigned sm[];
    const int t    = threadIdx.x;
    const int lane = t & 31;
    const int warp = t >> 5;
    const int wm   = warp >> 2;      // 0..1
    const int wn   = warp & 3;       // 0..3
    const int brow = blockIdx.x * 128;
    const int gidx = blockIdx.y;     // group / column block
    const int bcol = gidx * DH_;

    // ---- producer (A): thread -> row pr, k-half pkh ----
    const int pr   = t >> 1;            // 0..127
    const int pkh  = (t & 1) << 4;      // 0 / 16
    const int pks  = t & 1;             // k16 step
    const int pmg  = pr >> 4;           // m-tile 0..7
    const int plr  = pr & 15;
    const int ablk0 = (pmg * 2 + pks) * ABLK;
    const int preg0 = (plr >> 3) & 1;
    const int plf   = (plr & 7) << 2;

    // ---- producer (B): thread -> n-group bng, k-pair bkp ----
    const int bng  = t >> 4;            // 0..15
    const int bkp  = t & 15;            // 0..15
    const int bks  = bkp >> 3;
    const int breg = (bkp >> 2) & 1;
    const int btig = bkp & 3;
    const int bblk0 = (bng * 2 + bks) * ABLK;

    const float* Aptr = A + (size_t)(brow + pr) * E_ + pkh;
    const float* Wptr = W + (size_t)(2 * bkp) * E_ + bcol + bng * 8;

    float av[16], wv[16];
    #pragma unroll
    for (int i = 0; i < 4; ++i)
        *(float4*)&av[i * 4] = *(const float4*)(Aptr + i * 4);
    #pragma unroll
    for (int i = 0; i < 2; ++i)
        *(float4*)&wv[i * 4] = *(const float4*)(Wptr + i * 4);
    #pragma unroll
    for (int i = 0; i < 2; ++i)
        *(float4*)&wv[8 + i * 4] = *(const float4*)(Wptr + E_ + i * 4);

    float acc[4][4][4];
    #pragma unroll
    for (int mt = 0; mt < 4; ++mt)
        #pragma unroll
        for (int nt = 0; nt < 4; ++nt)
            #pragma unroll
            for (int c = 0; c < 4; ++c) acc[mt][nt][c] = 0.f;

    auto store_tile = [&](int buf) {
        unsigned* Ahi = sm + buf * BUF_WORDS;
        unsigned* Alo = Ahi + A_WORDS;
        unsigned* Bhi = Ahi + 2 * A_WORDS;
        unsigned* Blo = Ahi + 2 * A_WORDS + B_WORDS;
        #pragma unroll
        for (int p = 0; p < 8; ++p) {
            unsigned hi, lo;
            split2(av[2 * p], av[2 * p + 1], hi, lo);
            int lf  = plf | (p & 3);
            int reg = preg0 | ((p >> 2) << 1);
            int w   = (ablk0 + lf) * 4 + reg;
            Ahi[w] = hi;  Alo[w] = lo;
        }
        #pragma unroll
        for (int j = 0; j < 8; ++j) {
            unsigned hi, lo;
            split2(wv[j], wv[8 + j], hi, lo);     // low half = smaller k
            int lf = (j << 2) | btig;
            int w  = (bblk0 + lf) * 2 + breg;
            Bhi[w] = hi;  Blo[w] = lo;
        }
    };

    store_tile(0);
    __syncthreads();

    for (int kt = 0; kt < 32; ++kt) {
        const unsigned* Ahi = sm + (kt & 1) * BUF_WORDS;
        const unsigned* Alo = Ahi + A_WORDS;
        const unsigned* Bhi = Ahi + 2 * A_WORDS;
        const unsigned* Blo = Ahi + 2 * A_WORDS + B_WORDS;

        if (kt < 31) {
            const float* Ap = Aptr + (kt + 1) * 32;
            const float* Wp = Wptr + (size_t)(kt + 1) * 32 * E_;
            #pragma unroll
            for (int i = 0; i < 4; ++i)
                *(float4*)&av[i * 4] = *(const float4*)(Ap + i * 4);
            #pragma unroll
            for (int i = 0; i < 2; ++i)
                *(float4*)&wv[i * 4] = *(const float4*)(Wp + i * 4);
            #pragma unroll
            for (int i = 0; i < 2; ++i)
                *(float4*)&wv[8 + i * 4] = *(const float4*)(Wp + E_ + i * 4);
        }

        #pragma unroll
        for (int ks = 0; ks < 2; ++ks) {
            uint2 bh[4], bl[4];
            #pragma unroll
            for (int nt = 0; nt < 4; ++nt) {
                int blk = ((wn * 4 + nt) * 2 + ks) * ABLK + lane;
                bh[nt] = *(const uint2*)(Bhi + blk * 2);
                bl[nt] = *(const uint2*)(Blo + blk * 2);
            }
            #pragma unroll
            for (int mt = 0; mt < 4; ++mt) {
                int blk = ((wm * 4 + mt) * 2 + ks) * ABLK + lane;
                uint4 ah = *(const uint4*)(Ahi + blk * 4);
                uint4 al = *(const uint4*)(Alo + blk * 4);
                #pragma unroll
                for (int nt = 0; nt < 4; ++nt) {
                    mma16816(acc[mt][nt], ah, bh[nt]);
                    mma16816(acc[mt][nt], ah, bl[nt]);
                    mma16816(acc[mt][nt], al, bh[nt]);
                }
            }
        }

        if (kt < 31) store_tile((kt + 1) & 1);
        __syncthreads();
    }

    // ---------------- epilogue: bias + CELU -> stage -> GroupNorm -> out ------
    float* stage = (float*)sm;          // [128][130]
    const int g   = lane >> 2;
    const int tig = lane & 3;

    #pragma unroll
    for (int mt = 0; mt < 4; ++mt) {
        int row = wm * 64 + mt * 16 + g;
        #pragma unroll
        for (int nt = 0; nt < 4; ++nt) {
            int col = wn * 32 + nt * 8 + tig * 2;
            float2 bv = *(const float2*)(bias + bcol + col);
            float x0 = acc[mt][nt][0] + bv.x;
            float x1 = acc[mt][nt][1] + bv.y;
            float x2 = acc[mt][nt][2] + bv.x;
            float x3 = acc[mt][nt][3] + bv.y;
            x0 = (x0 > 0.f) ? x0 : 1.3f * expm1f(x0 * (1.f / 1.3f));
            x1 = (x1 > 0.f) ? x1 : 1.3f * expm1f(x1 * (1.f / 1.3f));
            x2 = (x2 > 0.f) ? x2 : 1.3f * expm1f(x2 * (1.f / 1.3f));
            x3 = (x3 > 0.f) ? x3 : 1.3f * expm1f(x3 * (1.f / 1.3f));
            *(float2*)&stage[row * 130 + col]       = make_float2(x0, x1);
            *(float2*)&stage[(row + 8) * 130 + col] = make_float2(x2, x3);
        }
    }
    __syncthreads();

    // each warp normalizes 16 rows
    for (int rr = 0; rr < 16; ++rr) {
        int row = warp * 16 + rr;
        float x[4];
        #pragma unroll
        for (int i = 0; i < 4; ++i) x[i] = stage[row * 130 + lane + 32 * i];
        float s = 0.f, s2 = 0.f;
        #pragma unroll
        for (int i = 0; i < 4; ++i) { s += x[i]; s2 += x[i] * x[i]; }
        #pragma unroll
        for (int o = 16; o; o >>= 1) {
            s  += __shfl_xor_sync(0xffffffffu, s,  o);
            s2 += __shfl_xor_sync(0xffffffffu, s2, o);
        }
        float mean = s * (1.f / 128.f);
        float var  = s2 * (1.f / 128.f) - mean * mean;
        float rstd = rsqrtf(var + 1e-5f);
        int rg = brow + row;
        int b  = rg / Mp;
        int m  = rg - b * Mp;
        float* op = out + (((size_t)b * H_ + gidx) * Mp + m) * DH_;
        #pragma unroll
        for (int i = 0; i < 4; ++i) {
            int c = lane + 32 * i;
            op[c] = (x[i] - mean) * rstd * gw[bcol + c] + gb[bcol + c];
        }
    }
}

// ---------------- fused back half: one block per (b,h) -----------------------
__global__ __launch_bounds__(256) void attn_kernel(
    const float* __restrict__ qt,  const float* __restrict__ v1t,
    const float* __restrict__ kt,  const float* __restrict__ v2t,
    const int*   __restrict__ mask,
    const float* __restrict__ Wb,  const float* __restrict__ bb,
    const float* __restrict__ Ws,  const float* __restrict__ bs,
    const float* __restrict__ Wc,  const float* __restrict__ bc,
    float* __restrict__ out)
{
    const int bh  = blockIdx.x;
    const int b   = bh >> 3;
    const int t   = threadIdx.x;
    const int sub = t >> 6;
    const int mid = t & 63;

    __shared__ __align__(16) float Wb_s[DH_ * MID_];
    __shared__ __align__(16) float q_s[DH_];
    __shared__ __align__(16) float a_s[4][DH_];
    __shared__ float mk_s[M_];
    __shared__ float s_s[M_];
    __shared__ float Ws_s[MID_];
    __shared__ float red_s[8];
    __shared__ float red2[8];
    __shared__ float pool4[4][MID_];
    __shared__ float pool_s[MID_];
    __shared__ float vp_s[256];
    __shared__ float sc_s[1];

    for (int i = t; i < DH_ * MID_; i += 256) Wb_s[i] = Wb[i];
    if (t < DH_)  q_s[t]  = qt[(size_t)bh * DH_ + t];
    if (t < MID_) Ws_s[t] = Ws[t];

    float mv = 0.f;
    if (t < M_) { mv = (float)mask[b * M_ + t]; mk_s[t] = mv; }
    float r = mv;
    #pragma unroll
    for (int o = 16; o; o >>= 1) r += __shfl_xor_sync(0xffffffffu, r, o);
    if ((t & 31) == 0) red2[t >> 5] = r;
    __syncthreads();
    if (t == 0) {
        float smk = 0.f;
        #pragma unroll
        for (int i = 0; i < 8; ++i) smk += red2[i];
        sc_s[0] = smk;
    }
    __syncthreads();

    const float bsv = bs[0];
    const float bbv = bb[mid];
    const float wsv = Ws_s[mid];
    const float* kbase  = kt  + (size_t)bh * M_ * DH_;
    const float* v2base = v2t + (size_t)bh * M_ * DH_;
    float pool_reg = 0.f;

    for (int m0 = 0; m0 < M_; m0 += 4) {
        const int m = m0 + sub;
        const float* krow = kbase + (size_t)m * DH_;
        a_s[sub][mid]      = q_s[mid]      * krow[mid];
        a_s[sub][mid + 64] = q_s[mid + 64] * krow[mid + 64];
        __syncthreads();

        const float* asub = a_s[sub];
        float h = bbv;
        #pragma unroll
        for (int d4 = 0; d4 < 32; ++d4) {
            float4 a4 = *(const float4*)(asub + (d4 << 2));
            h = fmaf(a4.x, Wb_s[((d4 << 2) + 0) * MID_ + mid], h);
            h = fmaf(a4.y, Wb_s[((d4 << 2) + 1) * MID_ + mid], h);
            h = fmaf(a4.z, Wb_s[((d4 << 2) + 2) * MID_ + mid], h);
            h = fmaf(a4.w, Wb_s[((d4 << 2) + 3) * MID_ + mid], h);
        }
        h = fmaxf(h, 0.f);
        pool_reg += h * mk_s[m];

        float sv = h * wsv;
        #pragma unroll
        for (int o = 16; o; o >>= 1) sv += __shfl_xor_sync(0xffffffffu, sv, o);
        if ((t & 31) == 0) red_s[t >> 5] = sv;
        __syncthreads();
        if (mid == 0) {
            float tot = red_s[sub * 2] + red_s[sub * 2 + 1] + bsv;
            s_s[m] = (mk_s[m] != 0.f) ? tot : -1e9f;
        }
    }
    pool4[sub][mid] = pool_reg;
    __syncthreads();
    if (t < MID_) {
        float p = pool4[0][t] + pool4[1][t] + pool4[2][t] + pool4[3][t];
        pool_s[t] = p / sc_s[0];
    }

    float xv = (t < M_) ? s_s[t] : -3.4e38f;
    float mx = xv;
    #pragma unroll
    for (int o = 16; o; o >>= 1) mx = fmaxf(mx, __shfl_xor_sync(0xffffffffu, mx, o));
    if ((t & 31) == 0) red2[t >> 5] = mx;
    __syncthreads();
    mx = red2[0];
    #pragma unroll
    for (int i = 1; i < 8; ++i) mx = fmaxf(mx, red2[i]);
    float e  = (t < M_) ? expf(xv - mx) : 0.f;
    float zs = e;
    #pragma unroll
    for (int o = 16; o; o >>= 1) zs += __shfl_xor_sync(0xffffffffu, zs, o);
    __syncthreads();
    if ((t & 31) == 0) red2[t >> 5] = zs;
    __syncthreads();
    float Z = red2[0] + red2[1] + red2[2] + red2[3] +
              red2[4] + red2[5] + red2[6] + red2[7];
    if (t < M_) s_s[t] = e / Z;
    __syncthreads();

    {
        int d = t & 127, half = t >> 7;
        float acc2 = 0.f;
        for (int m = half; m < M_; m += 2)
            acc2 += s_s[m] * v2base[(size_t)m * DH_ + d];
        vp_s[t] = acc2;
    }
    __syncthreads();

    if (t < DH_) {
        float v2p = vp_s[t] + vp_s[t + 128];
        float ac = bc[t];
        #pragma unroll
        for (int midi = 0; midi < MID_; ++midi)
            ac = fmaf(pool_s[midi], Wc[midi * DH_ + t], ac);
        ac = 1.0f / (1.0f + expf(-ac));
        out[(size_t)bh * DH_ + t] = v1t[(size_t)bh * DH_ + t] * v2p * ac;
    }
}

// ------------------------------- launcher ------------------------------------
extern "C" void kernel_launch(void* const* d_in, const int* in_sizes, int n_in,
                              void* d_out, int out_size)
{
    (void)in_sizes; (void)n_in; (void)out_size;
    const float* query  = (const float*)d_in[0];
    const float* key    = (const float*)d_in[1];
    const int*   mask   = (const int*)  d_in[2];
    const float* value1 = (const float*)d_in[3];
    const float* value2 = (const float*)d_in[4];
    const float* Wq   = (const float*)d_in[5];
    const float* bq   = (const float*)d_in[6];
    const float* gq_w = (const float*)d_in[7];
    const float* gq_b = (const float*)d_in[8];
    const float* Wk   = (const float*)d_in[9];
    const float* bk   = (const float*)d_in[10];
    const float* gk_w = (const float*)d_in[11];
    const float* gk_b = (const float*)d_in[12];
    const float* Wv1  = (const float*)d_in[13];
    const float* bv1  = (const float*)d_in[14];
    const float* gv1_w= (const float*)d_in[15];
    const float* gv1_b= (const float*)d_in[16];
    const float* Wv2  = (const float*)d_in[17];
    const float* bv2  = (const float*)d_in[18];
    const float* gv2_w= (const float*)d_in[19];
    const float* gv2_b= (const float*)d_in[20];
    const float* Wb   = (const float*)d_in[21];
    const float* bb   = (const float*)d_in[22];
    const float* Ws   = (const float*)d_in[23];
    const float* bs   = (const float*)d_in[24];
    const float* Wc   = (const float*)d_in[25];
    const float* bc   = (const float*)d_in[26];

    float *ktp, *v2tp, *qtp, *v1tp;
    cudaGetSymbolAddress((void**)&ktp,  g_kt);
    cudaGetSymbolAddress((void**)&v2tp, g_v2t);
    cudaGetSymbolAddress((void**)&qtp,  g_qt);
    cudaGetSymbolAddress((void**)&v1tp, g_v1t);

    cudaFuncSetAttribute(gemm_fused,
                         cudaFuncAttributeMaxDynamicSharedMemorySize, SMEM_BYTES);

    dim3 gBig(NBIG / 128, 8);     // (392, 8)
    dim3 gSmall(B_ / 128, 8);     // (2, 8)

    gemm_fused<<<gBig,   256, SMEM_BYTES>>>(key,    Wk,  bk,  gk_w,  gk_b,  ktp,  M_);
    gemm_fused<<<gBig,   256, SMEM_BYTES>>>(value2, Wv2, bv2, gv2_w, gv2_b, v2tp, M_);
    gemm_fused<<<gSmall, 256, SMEM_BYTES>>>(query,  Wq,  bq,  gq_w,  gq_b,  qtp,  1);
    gemm_fused<<<gSmall, 256, SMEM_BYTES>>>(value1, Wv1, bv1, gv1_w, gv1_b, v1tp, 1);

    attn_kernel<<<B_ * H_, 256>>>(qtp, v1tp, ktp, v2tp, mask,
                                  Wb, bb, Ws, bs, Wc, bc, (float*)d_out);
}

// round 4
// speedup vs baseline: 1.7746x; 1.7746x over previous
#include <cuda_runtime.h>
#include <cuda_bf16.h>
#include <math.h>

#define B_    256
#define M_    196
#define E_    1024
#define H_    8
#define DH_   128
#define MID_  64
#define NBIG  (B_ * M_)   // 50176
#define RB_BIG (NBIG / 128)   // 392

// ---------------- persistent scratch (no allocations allowed) -----------------
__device__ float    g_kt [(size_t)NBIG * E_];   // k  [B,H,M,Dh]
__device__ float    g_v2t[(size_t)NBIG * E_];   // v2 [B,H,M,Dh]
__device__ float    g_qt [(size_t)B_ * E_];     // q  [B,H,Dh]
__device__ float    g_v1t[(size_t)B_ * E_];     // v1 [B,H,Dh]
__device__ unsigned g_apack[(size_t)RB_BIG * 32 * 4096];  // packed A (bf16 hi/lo)
__device__ unsigned g_wpack[(size_t)8 * 32 * 4096];       // packed W

// chunk layout (4096 words): [0,2048) hi fragments, [2048,4096) lo fragments
// smem buffer (8192 words): [A hi|A lo|B hi|B lo], two buffers = 64 KB

#define CP_ASYNC16(sa, gp) \
    asm volatile("cp.async.cg.shared.global [%0], [%1], 16;" :: "r"(sa), "l"(gp))
#define CP_COMMIT() asm volatile("cp.async.commit_group;")
#define CP_WAIT(n)  asm volatile("cp.async.wait_group %0;" :: "n"(n))

__device__ __forceinline__ void split2(float f0, float f1,
                                       unsigned &hi, unsigned &lo)
{
    __nv_bfloat16 h0 = __float2bfloat16(f0);
    __nv_bfloat16 h1 = __float2bfloat16(f1);
    float r0 = f0 - __bfloat162float(h0);
    float r1 = f1 - __bfloat162float(h1);
    __nv_bfloat16 l0 = __float2bfloat16(r0);
    __nv_bfloat16 l1 = __float2bfloat16(r1);
    hi = (unsigned)__bfloat16_as_ushort(h0) |
         ((unsigned)__bfloat16_as_ushort(h1) << 16);
    lo = (unsigned)__bfloat16_as_ushort(l0) |
         ((unsigned)__bfloat16_as_ushort(l1) << 16);
}

__device__ __forceinline__ void mma16816(float* c, uint4 a, uint2 b)
{
    asm volatile(
        "mma.sync.aligned.m16n8k16.row.col.f32.bf16.bf16.f32 "
        "{%0,%1,%2,%3}, {%4,%5,%6,%7}, {%8,%9}, {%0,%1,%2,%3};\n"
        : "+f"(c[0]), "+f"(c[1]), "+f"(c[2]), "+f"(c[3])
        : "r"(a.x), "r"(a.y), "r"(a.z), "r"(a.w), "r"(b.x), "r"(b.y));
}

// =============================================================================
// pack A: fp32 [R,1024] row-major -> fragment-layout bf16 hi/lo chunks.
// grid (R/128, 32), 128 threads. Thread t emits 16 hi + 16 lo consecutive
// words at chunk offset t*16 (fully coalesced 64B stores).
// =============================================================================
__global__ __launch_bounds__(128) void pack_a_kernel(
    const float* __restrict__ A, unsigned* __restrict__ dst)
{
    const int rb = blockIdx.x, kt = blockIdx.y, t = threadIdx.x;
    const int mg = t >> 4;            // 16-row group
    const int ks = (t >> 3) & 1;      // k16 half within BK=32
    const int r0 = rb * 128 + mg * 16 + (t & 7);

    const float* p0 = A + (size_t)r0 * E_ + kt * 32 + ks * 16;
    const float* p1 = p0 + (size_t)8 * E_;
    float a0[16], a1[16];
    #pragma unroll
    for (int i = 0; i < 4; ++i) *(float4*)&a0[i*4] = *(const float4*)(p0 + i*4);
    #pragma unroll
    for (int i = 0; i < 4; ++i) *(float4*)&a1[i*4] = *(const float4*)(p1 + i*4);

    unsigned hiw[16], low[16];
    #pragma unroll
    for (int i = 0; i < 16; ++i) {
        const float* ar = (i & 1) ? a1 : a0;
        int p = (i >> 2) | (((i >> 1) & 1) << 2);
        split2(ar[2*p], ar[2*p + 1], hiw[i], low[i]);
    }
    unsigned* base = dst + ((size_t)rb * 32 + kt) * 4096 + t * 16;
    #pragma unroll
    for (int i = 0; i < 4; ++i) *(uint4*)(base + i*4)        = *(uint4*)&hiw[i*4];
    #pragma unroll
    for (int i = 0; i < 4; ++i) *(uint4*)(base + 2048 + i*4) = *(uint4*)&low[i*4];
}

// =============================================================================
// pack W: fp32 [1024,1024] row-major -> B fragment-layout bf16 hi/lo chunks.
// grid (8 colblocks, 32 ktiles), 256 threads. Mirrors original producer map.
// =============================================================================
__global__ __launch_bounds__(256) void pack_w_kernel(
    const float* __restrict__ W, unsigned* __restrict__ dst)
{
    const int cb = blockIdx.x, kt = blockIdx.y, t = threadIdx.x;
    const int bng = t >> 4, bkp = t & 15;
    const int bks = bkp >> 3, breg = (bkp >> 2) & 1, btig = bkp & 3;
    const int krow = kt * 32 + 2 * bkp;

    const float* p0 = W + (size_t)krow * E_ + cb * 128 + bng * 8;
    float w0[8], w1[8];
    #pragma unroll
    for (int i = 0; i < 2; ++i) *(float4*)&w0[i*4] = *(const float4*)(p0 + i*4);
    #pragma unroll
    for (int i = 0; i < 2; ++i) *(float4*)&w1[i*4] = *(const float4*)(p0 + E_ + i*4);

    unsigned* base = dst + ((size_t)cb * 32 + kt) * 4096;
    #pragma unroll
    for (int j = 0; j < 8; ++j) {
        unsigned hi, lo;
        split2(w0[j], w1[j], hi, lo);
        int w = ((bng * 2 + bks) * 32 + ((j << 2) | btig)) * 2 + breg;
        base[w]        = hi;
        base[2048 + w] = lo;
    }
}

// =============================================================================
// GEMM on packed operands + bias + CELU + GroupNorm + transposed store.
// grid (8 colblocks, R/128), 256 threads, 2 CTAs/SM. cp.async double buffer.
// =============================================================================
__global__ __launch_bounds__(256, 2) void gemm_packed(
    const unsigned* __restrict__ Apk, const unsigned* __restrict__ Wpk,
    const float* __restrict__ bias, const float* __restrict__ gw,
    const float* __restrict__ gb, float* __restrict__ out, int Mp)
{
    extern __shared__ unsigned sm[];
    const int t    = threadIdx.x;
    const int lane = t & 31;
    const int warp = t >> 5;
    const int wm   = warp >> 2;       // 0..1
    const int wn   = warp & 3;        // 0..3
    const int gidx = blockIdx.x;      // column block / group
    const int rb   = blockIdx.y;
    const int brow = rb * 128;
    const int bcol = gidx * DH_;

    const unsigned smbase = (unsigned)__cvta_generic_to_shared(sm);
    const unsigned* srcA0 = Apk + (size_t)rb   * 32 * 4096;
    const unsigned* srcB0 = Wpk + (size_t)gidx * 32 * 4096;

    float acc[4][4][4];
    #pragma unroll
    for (int mt = 0; mt < 4; ++mt)
        #pragma unroll
        for (int nt = 0; nt < 4; ++nt)
            #pragma unroll
            for (int c = 0; c < 4; ++c) acc[mt][nt][c] = 0.f;

    auto copy_chunk = [&](int buf, int kt) {
        const uint4* sa = (const uint4*)(srcA0 + (size_t)kt * 4096);
        const uint4* sb = (const uint4*)(srcB0 + (size_t)kt * 4096);
        unsigned db = smbase + buf * 32768;
        #pragma unroll
        for (int i = 0; i < 4; ++i)
            CP_ASYNC16(db + (t + i * 256) * 16, sa + t + i * 256);
        #pragma unroll
        for (int i = 0; i < 4; ++i)
            CP_ASYNC16(db + 16384 + (t + i * 256) * 16, sb + t + i * 256);
    };

    copy_chunk(0, 0);
    CP_COMMIT();

    for (int kt = 0; kt < 32; ++kt) {
        if (kt < 31) {
            copy_chunk((kt + 1) & 1, kt + 1);
            CP_COMMIT();
            CP_WAIT(1);
        } else {
            CP_WAIT(0);
        }
        __syncthreads();

        const unsigned* Ahi = sm + (kt & 1) * 8192;
        const unsigned* Alo = Ahi + 2048;
        const unsigned* Bhi = Ahi + 4096;
        const unsigned* Blo = Ahi + 6144;

        #pragma unroll
        for (int ks = 0; ks < 2; ++ks) {
            uint2 bh[4], bl[4];
            #pragma unroll
            for (int nt = 0; nt < 4; ++nt) {
                int blk = ((wn * 4 + nt) * 2 + ks) * 32 + lane;
                bh[nt] = *(const uint2*)(Bhi + blk * 2);
                bl[nt] = *(const uint2*)(Blo + blk * 2);
            }
            #pragma unroll
            for (int mt = 0; mt < 4; ++mt) {
                int blk = ((wm * 4 + mt) * 2 + ks) * 32 + lane;
                uint4 ah = *(const uint4*)(Ahi + blk * 4);
                uint4 al = *(const uint4*)(Alo + blk * 4);
                #pragma unroll
                for (int nt = 0; nt < 4; ++nt) {
                    mma16816(acc[mt][nt], ah, bh[nt]);
                    mma16816(acc[mt][nt], ah, bl[nt]);
                    mma16816(acc[mt][nt], al, bh[nt]);
                }
            }
        }
        __syncthreads();
    }

    // ---------------- epilogue: bias+CELU in regs, GroupNorm, store ----------
    float* ps = (float*)sm;            // [128][4] partial sums
    float* pq = ps + 512;              // [128][4] partial sumsq
    float* mv = ps + 1024;             // [128] mean
    float* rv = ps + 1152;             // [128] rstd

    const int g4 = lane >> 2;
    const int q4 = lane & 3;

    float s0[4], q0[4], s1[4], q1[4];
    #pragma unroll
    for (int mt = 0; mt < 4; ++mt) {
        float a0 = 0.f, b0 = 0.f, a1 = 0.f, b1 = 0.f;
        #pragma unroll
        for (int nt = 0; nt < 4; ++nt) {
            int col = wn * 32 + nt * 8 + q4 * 2;
            float2 bv = *(const float2*)(bias + bcol + col);
            float* c = acc[mt][nt];
            float x0 = c[0] + bv.x, x1 = c[1] + bv.y;
            float x2 = c[2] + bv.x, x3 = c[3] + bv.y;
            x0 = (x0 > 0.f) ? x0 : 1.3f * expm1f(x0 * (1.f/1.3f));
            x1 = (x1 > 0.f) ? x1 : 1.3f * expm1f(x1 * (1.f/1.3f));
            x2 = (x2 > 0.f) ? x2 : 1.3f * expm1f(x2 * (1.f/1.3f));
            x3 = (x3 > 0.f) ? x3 : 1.3f * expm1f(x3 * (1.f/1.3f));
            c[0] = x0; c[1] = x1; c[2] = x2; c[3] = x3;
            a0 += x0 + x1;  b0 += x0*x0 + x1*x1;
            a1 += x2 + x3;  b1 += x2*x2 + x3*x3;
        }
        #pragma unroll
        for (int o = 1; o <= 2; o <<= 1) {
            a0 += __shfl_xor_sync(0xffffffffu, a0, o);
            b0 += __shfl_xor_sync(0xffffffffu, b0, o);
            a1 += __shfl_xor_sync(0xffffffffu, a1, o);
            b1 += __shfl_xor_sync(0xffffffffu, b1, o);
        }
        s0[mt] = a0; q0[mt] = b0; s1[mt] = a1; q1[mt] = b1;
    }
    if (q4 == 0) {
        #pragma unroll
        for (int mt = 0; mt < 4; ++mt) {
            int r0 = wm * 64 + mt * 16 + g4;
            ps[r0 * 4 + wn] = s0[mt];  pq[r0 * 4 + wn] = q0[mt];
            ps[(r0+8)*4 + wn] = s1[mt]; pq[(r0+8)*4 + wn] = q1[mt];
        }
    }
    __syncthreads();
    if (t < 128) {
        float s = ps[t*4] + ps[t*4+1] + ps[t*4+2] + ps[t*4+3];
        float q = pq[t*4] + pq[t*4+1] + pq[t*4+2] + pq[t*4+3];
        float mean = s * (1.f / 128.f);
        float var  = q * (1.f / 128.f) - mean * mean;
        mv[t] = mean;
        rv[t] = rsqrtf(var + 1e-5f);
    }
    __syncthreads();

    #pragma unroll
    for (int mt = 0; mt < 4; ++mt) {
        int row0 = wm * 64 + mt * 16 + g4;
        int row1 = row0 + 8;
        float m0 = mv[row0], r0v = rv[row0];
        float m1 = mv[row1], r1v = rv[row1];
        int rg0 = brow + row0, rg1 = brow + row1;
        int b0i = rg0 / Mp, mm0 = rg0 - b0i * Mp;
        int b1i = rg1 / Mp, mm1 = rg1 - b1i * Mp;
        float* op0 = out + (((size_t)b0i * H_ + gidx) * Mp + mm0) * DH_;
        float* op1 = out + (((size_t)b1i * H_ + gidx) * Mp + mm1) * DH_;
        #pragma unroll
        for (int nt = 0; nt < 4; ++nt) {
            int col = wn * 32 + nt * 8 + q4 * 2;
            float2 gwv = *(const float2*)(gw + bcol + col);
            float2 gbv = *(const float2*)(gb + bcol + col);
            float* c = acc[mt][nt];
            float2 y0 = make_float2((c[0] - m0) * r0v * gwv.x + gbv.x,
                                    (c[1] - m0) * r0v * gwv.y + gbv.y);
            float2 y1 = make_float2((c[2] - m1) * r1v * gwv.x + gbv.x,
                                    (c[3] - m1) * r1v * gwv.y + gbv.y);
            *(float2*)(op0 + col) = y0;
            *(float2*)(op1 + col) = y1;
        }
    }
}

// ---------------- fused back half: one block per (b,h) -----------------------
__global__ __launch_bounds__(256) void attn_kernel(
    const float* __restrict__ qt,  const float* __restrict__ v1t,
    const float* __restrict__ kt,  const float* __restrict__ v2t,
    const int*   __restrict__ mask,
    const float* __restrict__ Wb,  const float* __restrict__ bb,
    const float* __restrict__ Ws,  const float* __restrict__ bs,
    const float* __restrict__ Wc,  const float* __restrict__ bc,
    float* __restrict__ out)
{
    const int bh  = blockIdx.x;
    const int b   = bh >> 3;
    const int t   = threadIdx.x;
    const int sub = t >> 6;
    const int mid = t & 63;

    __shared__ __align__(16) float Wb_s[DH_ * MID_];
    __shared__ __align__(16) float q_s[DH_];
    __shared__ __align__(16) float a_s[4][DH_];
    __shared__ float mk_s[M_];
    __shared__ float s_s[M_];
    __shared__ float Ws_s[MID_];
    __shared__ float red_s[8];
    __shared__ float red2[8];
    __shared__ float pool4[4][MID_];
    __shared__ float pool_s[MID_];
    __shared__ float vp_s[256];
    __shared__ float sc_s[1];

    for (int i = t; i < DH_ * MID_; i += 256) Wb_s[i] = Wb[i];
    if (t < DH_)  q_s[t]  = qt[(size_t)bh * DH_ + t];
    if (t < MID_) Ws_s[t] = Ws[t];

    float mvx = 0.f;
    if (t < M_) { mvx = (float)mask[b * M_ + t]; mk_s[t] = mvx; }
    float r = mvx;
    #pragma unroll
    for (int o = 16; o; o >>= 1) r += __shfl_xor_sync(0xffffffffu, r, o);
    if ((t & 31) == 0) red2[t >> 5] = r;
    __syncthreads();
    if (t == 0) {
        float smk = 0.f;
        #pragma unroll
        for (int i = 0; i < 8; ++i) smk += red2[i];
        sc_s[0] = smk;
    }
    __syncthreads();

    const float bsv = bs[0];
    const float bbv = bb[mid];
    const float wsv = Ws_s[mid];
    const float* kbase  = kt  + (size_t)bh * M_ * DH_;
    const float* v2base = v2t + (size_t)bh * M_ * DH_;
    float pool_reg = 0.f;

    for (int m0 = 0; m0 < M_; m0 += 4) {
        const int m = m0 + sub;
        const float* krow = kbase + (size_t)m * DH_;
        a_s[sub][mid]      = q_s[mid]      * krow[mid];
        a_s[sub][mid + 64] = q_s[mid + 64] * krow[mid + 64];
        __syncthreads();

        const float* asub = a_s[sub];
        float h = bbv;
        #pragma unroll
        for (int d4 = 0; d4 < 32; ++d4) {
            float4 a4 = *(const float4*)(asub + (d4 << 2));
            h = fmaf(a4.x, Wb_s[((d4 << 2) + 0) * MID_ + mid], h);
            h = fmaf(a4.y, Wb_s[((d4 << 2) + 1) * MID_ + mid], h);
            h = fmaf(a4.z, Wb_s[((d4 << 2) + 2) * MID_ + mid], h);
            h = fmaf(a4.w, Wb_s[((d4 << 2) + 3) * MID_ + mid], h);
        }
        h = fmaxf(h, 0.f);
        pool_reg += h * mk_s[m];

        float sv = h * wsv;
        #pragma unroll
        for (int o = 16; o; o >>= 1) sv += __shfl_xor_sync(0xffffffffu, sv, o);
        if ((t & 31) == 0) red_s[t >> 5] = sv;
        __syncthreads();
        if (mid == 0) {
            float tot = red_s[sub * 2] + red_s[sub * 2 + 1] + bsv;
            s_s[m] = (mk_s[m] != 0.f) ? tot : -1e9f;
        }
    }
    pool4[sub][mid] = pool_reg;
    __syncthreads();
    if (t < MID_) {
        float p = pool4[0][t] + pool4[1][t] + pool4[2][t] + pool4[3][t];
        pool_s[t] = p / sc_s[0];
    }

    float xv = (t < M_) ? s_s[t] : -3.4e38f;
    float mx = xv;
    #pragma unroll
    for (int o = 16; o; o >>= 1) mx = fmaxf(mx, __shfl_xor_sync(0xffffffffu, mx, o));
    if ((t & 31) == 0) red2[t >> 5] = mx;
    __syncthreads();
    mx = red2[0];
    #pragma unroll
    for (int i = 1; i < 8; ++i) mx = fmaxf(mx, red2[i]);
    float e  = (t < M_) ? expf(xv - mx) : 0.f;
    float zs = e;
    #pragma unroll
    for (int o = 16; o; o >>= 1) zs += __shfl_xor_sync(0xffffffffu, zs, o);
    __syncthreads();
    if ((t & 31) == 0) red2[t >> 5] = zs;
    __syncthreads();
    float Z = red2[0] + red2[1] + red2[2] + red2[3] +
              red2[4] + red2[5] + red2[6] + red2[7];
    if (t < M_) s_s[t] = e / Z;
    __syncthreads();

    {
        int d = t & 127, half = t >> 7;
        float acc2 = 0.f;
        for (int m = half; m < M_; m += 2)
            acc2 += s_s[m] * v2base[(size_t)m * DH_ + d];
        vp_s[t] = acc2;
    }
    __syncthreads();

    if (t < DH_) {
        float v2p = vp_s[t] + vp_s[t + 128];
        float ac = bc[t];
        #pragma unroll
        for (int midi = 0; midi < MID_; ++midi)
            ac = fmaf(pool_s[midi], Wc[midi * DH_ + t], ac);
        ac = 1.0f / (1.0f + expf(-ac));
        out[(size_t)bh * DH_ + t] = v1t[(size_t)bh * DH_ + t] * v2p * ac;
    }
}

// ------------------------------- launcher ------------------------------------
extern "C" void kernel_launch(void* const* d_in, const int* in_sizes, int n_in,
                              void* d_out, int out_size)
{
    (void)in_sizes; (void)n_in; (void)out_size;
    const float* query  = (const float*)d_in[0];
    const float* key    = (const float*)d_in[1];
    const int*   mask   = (const int*)  d_in[2];
    const float* value1 = (const float*)d_in[3];
    const float* value2 = (const float*)d_in[4];
    const float* Wq   = (const float*)d_in[5];
    const float* bq   = (const float*)d_in[6];
    const float* gq_w = (const float*)d_in[7];
    const float* gq_b = (const float*)d_in[8];
    const float* Wk   = (const float*)d_in[9];
    const float* bk   = (const float*)d_in[10];
    const float* gk_w = (const float*)d_in[11];
    const float* gk_b = (const float*)d_in[12];
    const float* Wv1  = (const float*)d_in[13];
    const float* bv1  = (const float*)d_in[14];
    const float* gv1_w= (const float*)d_in[15];
    const float* gv1_b= (const float*)d_in[16];
    const float* Wv2  = (const float*)d_in[17];
    const float* bv2  = (const float*)d_in[18];
    const float* gv2_w= (const float*)d_in[19];
    const float* gv2_b= (const float*)d_in[20];
    const float* Wb   = (const float*)d_in[21];
    const float* bb   = (const float*)d_in[22];
    const float* Ws   = (const float*)d_in[23];
    const float* bs   = (const float*)d_in[24];
    const float* Wc   = (const float*)d_in[25];
    const float* bc   = (const float*)d_in[26];

    float *ktp, *v2tp, *qtp, *v1tp;
    unsigned *apk, *wpk;
    cudaGetSymbolAddress((void**)&ktp,  g_kt);
    cudaGetSymbolAddress((void**)&v2tp, g_v2t);
    cudaGetSymbolAddress((void**)&qtp,  g_qt);
    cudaGetSymbolAddress((void**)&v1tp, g_v1t);
    cudaGetSymbolAddress((void**)&apk,  g_apack);
    cudaGetSymbolAddress((void**)&wpk,  g_wpack);

    cudaFuncSetAttribute(gemm_packed,
                         cudaFuncAttributeMaxDynamicSharedMemorySize, 65536);

    dim3 packBig(RB_BIG, 32), packSmall(B_ / 128, 32), packW(8, 32);
    dim3 gBig(8, RB_BIG), gSmall(8, B_ / 128);

    // k projection
    pack_w_kernel<<<packW, 256>>>(Wk, wpk);
    pack_a_kernel<<<packBig, 128>>>(key, apk);
    gemm_packed<<<gBig, 256, 65536>>>(apk, wpk, bk, gk_w, gk_b, ktp, M_);
    // v2 projection
    pack_w_kernel<<<packW, 256>>>(Wv2, wpk);
    pack_a_kernel<<<packBig, 128>>>(value2, apk);
    gemm_packed<<<gBig, 256, 65536>>>(apk, wpk, bv2, gv2_w, gv2_b, v2tp, M_);
    // q projection
    pack_w_kernel<<<packW, 256>>>(Wq, wpk);
    pack_a_kernel<<<packSmall, 128>>>(query, apk);
    gemm_packed<<<gSmall, 256, 65536>>>(apk, wpk, bq, gq_w, gq_b, qtp, 1);
    // v1 projection
    pack_w_kernel<<<packW, 256>>>(Wv1, wpk);
    pack_a_kernel<<<packSmall, 128>>>(value1, apk);
    gemm_packed<<<gSmall, 256, 65536>>>(apk, wpk, bv1, gv1_w, gv1_b, v1tp, 1);

    attn_kernel<<<B_ * H_, 256>>>(qtp, v1tp, ktp, v2tp, mask,
                                  Wb, bb, Ws, bs, Wc, bc, (float*)d_out);
}